// round 7
// baseline (speedup 1.0000x reference)
#include <cuda_runtime.h>
#include <math.h>

#define BB 4
#define SS 4096
#define QEPS 1e-6f

// Scratch (no allocations allowed): pass-1 -> pass-2 hand-off.
__device__ float g_rmid[BB * SS * 2];
__device__ float g_k1v[BB * SS * 2];
__device__ float g_rowsum[BB * SS];

__device__ __forceinline__ float warpSum(float v) {
    v += __shfl_xor_sync(0xffffffffu, v, 16);
    v += __shfl_xor_sync(0xffffffffu, v, 8);
    v += __shfl_xor_sync(0xffffffffu, v, 4);
    v += __shfl_xor_sync(0xffffffffu, v, 2);
    v += __shfl_xor_sync(0xffffffffu, v, 1);
    return v;
}

// ---------------------------------------------------------------------------
// Pass 1: score = row-normalized causal relu(r·r); write score (268 MB),
// stash r_mid, k1, rowsum for pass 2.
// Block: 256 threads = 8 warps; each warp owns row pair (p, S-1-p) so the
// causal trip counts balance and one smem r_t load feeds both rows.
// ---------------------------------------------------------------------------
__global__ void __launch_bounds__(256)
qi_pass1(const float* __restrict__ r, const float* __restrict__ dt,
         float* __restrict__ score_out) {
    __shared__ __align__(16) float2 sr[SS];
    const int b   = blockIdx.y;
    const int tid = threadIdx.x;

    // Cooperative load of the whole batch row set (32 KB) as float4.
    {
        const float4* rb4 = (const float4*)(r + (size_t)b * SS * 2);
        float4* sr4 = (float4*)sr;
#pragma unroll
        for (int i = 0; i < (SS * 2 / 4) / 256; i++)
            sr4[tid + i * 256] = rb4[tid + i * 256];
    }
    __syncthreads();

    const int warp = tid >> 5, lane = tid & 31;
    const int pairId = blockIdx.x * 8 + warp;   // [0, SS/2)
    const int s0 = pairId;
    const int s1 = SS - 1 - pairId;             // s0 <= s1 always

    const float2 rs0 = sr[s0];
    const float2 rs1 = sr[s1];

    // --- accumulate pass (causal) ---
    float a0 = 0.f, ax0 = 0.f, ay0 = 0.f;
    float a1 = 0.f, ax1 = 0.f, ay1 = 0.f;
    for (int t = lane; t <= s1; t += 32) {
        float2 rt = sr[t];
        float d1 = fmaf(rs1.x, rt.x, rs1.y * rt.y);
        float v1 = fmaxf(d1, 0.f);
        a1 += v1; ax1 = fmaf(v1, rt.x, ax1); ay1 = fmaf(v1, rt.y, ay1);
        if (t <= s0) {
            float d0 = fmaf(rs0.x, rt.x, rs0.y * rt.y);
            float v0 = fmaxf(d0, 0.f);
            a0 += v0; ax0 = fmaf(v0, rt.x, ax0); ay0 = fmaf(v0, rt.y, ay0);
        }
    }
    a0 = warpSum(a0); ax0 = warpSum(ax0); ay0 = warpSum(ay0);
    a1 = warpSum(a1); ax1 = warpSum(ax1); ay1 = warpSum(ay1);

    const float inv0 = 1.0f / fmaxf(a0, QEPS);
    const float inv1 = 1.0f / fmaxf(a1, QEPS);

    if (lane == 0) {
        const float dtb = dt[b];
#pragma unroll
        for (int w = 0; w < 2; w++) {
            const int   s   = w ? s1 : s0;
            const float av  = w ? a1 : a0;
            const float axv = w ? ax1 : ax0;
            const float ayv = w ? ay1 : ay0;
            const float inv = w ? inv1 : inv0;
            const float2 rs = w ? rs1 : rs0;

            float cx = axv * inv, cy = ayv * inv;
            float k1x = dtb * cx; if (!isfinite(k1x)) k1x = 0.f;
            float k1y = dtb * cy; if (!isfinite(k1y)) k1y = 0.f;
            float rmx = rs.x + k1x; if (!isfinite(rmx)) rmx = rs.x;
            float rmy = rs.y + k1y; if (!isfinite(rmy)) rmy = rs.y;

            const size_t idx = (size_t)b * SS + s;
            ((float2*)g_rmid)[idx] = make_float2(rmx, rmy);
            ((float2*)g_k1v)[idx]  = make_float2(k1x, k1y);
            g_rowsum[idx] = av * inv;   // sum of normalized score row
        }
    }

    // --- write pass: both rows, float4 stores, one smem load feeds both ---
    float* out0 = score_out + ((size_t)b * SS + s0) * SS;
    float* out1 = score_out + ((size_t)b * SS + s1) * SS;
    for (int t0 = lane * 4; t0 < SS; t0 += 128) {
        float4 p = *(const float4*)(&sr[t0]);       // (x0,y0,x1,y1)
        float4 q = *(const float4*)(&sr[t0 + 2]);   // (x2,y2,x3,y3)
        float4 w0, w1;
        {
            float d = fmaf(rs0.x, p.x, rs0.y * p.y);
            w0.x = (t0 + 0 <= s0) ? fmaxf(d, 0.f) * inv0 : 0.f;
            float e = fmaf(rs1.x, p.x, rs1.y * p.y);
            w1.x = (t0 + 0 <= s1) ? fmaxf(e, 0.f) * inv1 : 0.f;
        }
        {
            float d = fmaf(rs0.x, p.z, rs0.y * p.w);
            w0.y = (t0 + 1 <= s0) ? fmaxf(d, 0.f) * inv0 : 0.f;
            float e = fmaf(rs1.x, p.z, rs1.y * p.w);
            w1.y = (t0 + 1 <= s1) ? fmaxf(e, 0.f) * inv1 : 0.f;
        }
        {
            float d = fmaf(rs0.x, q.x, rs0.y * q.y);
            w0.z = (t0 + 2 <= s0) ? fmaxf(d, 0.f) * inv0 : 0.f;
            float e = fmaf(rs1.x, q.x, rs1.y * q.y);
            w1.z = (t0 + 2 <= s1) ? fmaxf(e, 0.f) * inv1 : 0.f;
        }
        {
            float d = fmaf(rs0.x, q.z, rs0.y * q.w);
            w0.w = (t0 + 3 <= s0) ? fmaxf(d, 0.f) * inv0 : 0.f;
            float e = fmaf(rs1.x, q.z, rs1.y * q.w);
            w1.w = (t0 + 3 <= s1) ? fmaxf(e, 0.f) * inv1 : 0.f;
        }
        *(float4*)(out0 + t0) = w0;
        *(float4*)(out1 + t0) = w1;
    }
}

// ---------------------------------------------------------------------------
// Pass 2: repeat interaction on r_mid (no score output), then the Heun step,
// radius clamp, and r_final write (tiny).
// ---------------------------------------------------------------------------
__global__ void __launch_bounds__(256)
qi_pass2(const float* __restrict__ r, const float* __restrict__ dt,
         float* __restrict__ rfinal_out) {
    __shared__ __align__(16) float2 sm[SS];
    const int b   = blockIdx.y;
    const int tid = threadIdx.x;

    {
        const float4* mb4 = (const float4*)(g_rmid + (size_t)b * SS * 2);
        float4* sm4 = (float4*)sm;
#pragma unroll
        for (int i = 0; i < (SS * 2 / 4) / 256; i++)
            sm4[tid + i * 256] = mb4[tid + i * 256];
    }
    __syncthreads();

    const int warp = tid >> 5, lane = tid & 31;
    const int pairId = blockIdx.x * 8 + warp;
    const int s0 = pairId;
    const int s1 = SS - 1 - pairId;

    const float2 m0 = sm[s0];
    const float2 m1 = sm[s1];

    float a0 = 0.f, ax0 = 0.f, ay0 = 0.f;
    float a1 = 0.f, ax1 = 0.f, ay1 = 0.f;
    for (int t = lane; t <= s1; t += 32) {
        float2 mt = sm[t];
        float d1 = fmaf(m1.x, mt.x, m1.y * mt.y);
        float v1 = fmaxf(d1, 0.f);
        a1 += v1; ax1 = fmaf(v1, mt.x, ax1); ay1 = fmaf(v1, mt.y, ay1);
        if (t <= s0) {
            float d0 = fmaf(m0.x, mt.x, m0.y * mt.y);
            float v0 = fmaxf(d0, 0.f);
            a0 += v0; ax0 = fmaf(v0, mt.x, ax0); ay0 = fmaf(v0, mt.y, ay0);
        }
    }
    a0 = warpSum(a0); ax0 = warpSum(ax0); ay0 = warpSum(ay0);
    a1 = warpSum(a1); ax1 = warpSum(ax1); ay1 = warpSum(ay1);

    if (lane == 0) {
        const float dtb = dt[b];
#pragma unroll
        for (int w = 0; w < 2; w++) {
            const int   s   = w ? s1 : s0;
            const float av  = w ? a1 : a0;
            const float axv = w ? ax1 : ax0;
            const float ayv = w ? ay1 : ay0;

            const float inv = 1.0f / fmaxf(av, QEPS);
            float k2x = dtb * (axv * inv); if (!isfinite(k2x)) k2x = 0.f;
            float k2y = dtb * (ayv * inv); if (!isfinite(k2y)) k2y = 0.f;

            const size_t idx = (size_t)b * SS + s;
            const float2 k1 = ((const float2*)g_k1v)[idx];
            const float2 r0 = ((const float2*)r)[idx];
            const float rowsum = g_rowsum[idx];

            float rnx = r0.x + 0.5f * (k1.x + k2x);
            float rny = r0.y + 0.5f * (k1.y + k2y);

            float nr = fmaxf(sqrtf(rnx * rnx + rny * rny), QEPS);
            float adj = rowsum * 0.01f;                      // RADIUS_UPDATE_RATE
            float ar = fminf(fmaxf(nr + adj, 0.1f), 2.0f);   // MIN/MAX_RADIUS
            float sc = ar / nr;

            float fx = rnx * sc; if (!isfinite(fx)) fx = r0.x;
            float fy = rny * sc; if (!isfinite(fy)) fy = r0.y;
            ((float2*)rfinal_out)[idx] = make_float2(fx, fy);
        }
    }
}

extern "C" void kernel_launch(void* const* d_in, const int* in_sizes, int n_in,
                              void* d_out, int out_size) {
    // metadata order: r_embed [B*S*2], dt [B]; be defensive about order.
    const float* r  = (const float*)d_in[0];
    const float* dt = (const float*)d_in[1];
    if (in_sizes[0] == BB && in_sizes[1] == BB * SS * 2) {
        r  = (const float*)d_in[1];
        dt = (const float*)d_in[0];
    }
    float* out    = (float*)d_out;
    float* rfinal = out;                          // [B,S,2]
    float* score  = out + (size_t)BB * SS * 2;    // [B,S,S]

    dim3 grid(SS / 16, BB);   // 8 warps/block * 2 rows/warp = 16 rows/block
    qi_pass1<<<grid, 256>>>(r, dt, score);
    qi_pass2<<<grid, 256>>>(r, dt, rfinal);
}